// round 14
// baseline (speedup 1.0000x reference)
#include <cuda_runtime.h>
#include <cuda_fp16.h>
#include <cstdint>

constexpr int S_  = 2048;
constexpr int B_  = 4;
constexpr int D_  = 1024;
constexpr int H_  = 16;
constexpr int DH_ = 64;
#define SCALE_F 0.125f   // 1/sqrt(64)

// ---------------- fp16 scratch (device globals) -----------------------------
__device__ __half g_Xh[(size_t)B_ * S_ * D_];        // [B*S, D]  (m = b*S+s)
__device__ __half g_Wqkvh[(size_t)3 * D_ * D_];      // [3D, D]
__device__ __half g_Wprojh[(size_t)D_ * D_];         // [D, D]
__device__ __half g_Qh[(size_t)B_ * H_ * S_ * DH_];  // [B,H,S,DH]   (pre-scaled)
__device__ __half g_Kh[(size_t)B_ * H_ * S_ * DH_];  // [B,H,j,DH]   compacted
__device__ __half g_Vh[(size_t)B_ * H_ * S_ * DH_];  // [B,H,j,DH]   compacted
__device__ __half g_attnh[(size_t)B_ * S_ * D_];     // [B*S, D]
__device__ int    g_kidx[(size_t)B_ * S_];           // compacted key indices
__device__ int    g_kcnt[B_];                        // kept-key counts

// ---------------- asm helpers ------------------------------------------------
__device__ __forceinline__ uint32_t s2u(const void* p) {
    return (uint32_t)__cvta_generic_to_shared(p);
}
__device__ __forceinline__ void cpa16(uint32_t d, const void* s) {
    asm volatile("cp.async.cg.shared.global [%0], [%1], 16;\n" :: "r"(d), "l"(s));
}
__device__ __forceinline__ void cpcommit() {
    asm volatile("cp.async.commit_group;\n");
}
template <int N> __device__ __forceinline__ void cpwait() {
    asm volatile("cp.async.wait_group %0;\n" :: "n"(N));
}
__device__ __forceinline__ void ldm4(unsigned& r0, unsigned& r1, unsigned& r2,
                                     unsigned& r3, uint32_t a) {
    asm volatile("ldmatrix.sync.aligned.m8n8.x4.shared.b16 {%0,%1,%2,%3},[%4];"
                 : "=r"(r0), "=r"(r1), "=r"(r2), "=r"(r3) : "r"(a));
}
__device__ __forceinline__ void ldm4t(unsigned& r0, unsigned& r1, unsigned& r2,
                                      unsigned& r3, uint32_t a) {
    asm volatile("ldmatrix.sync.aligned.m8n8.x4.trans.shared.b16 {%0,%1,%2,%3},[%4];"
                 : "=r"(r0), "=r"(r1), "=r"(r2), "=r"(r3) : "r"(a));
}
__device__ __forceinline__ void mma16(float* c, const unsigned* a, const unsigned* b) {
    asm volatile(
        "mma.sync.aligned.m16n8k16.row.col.f32.f16.f16.f32 "
        "{%0,%1,%2,%3},{%4,%5,%6,%7},{%8,%9},{%0,%1,%2,%3};"
        : "+f"(c[0]), "+f"(c[1]), "+f"(c[2]), "+f"(c[3])
        : "r"(a[0]), "r"(a[1]), "r"(a[2]), "r"(a[3]), "r"(b[0]), "r"(b[1]));
}

// ============================================================================
// Fused prep: X/W conversions (4 float4 per thread) + key compaction.
// ============================================================================
__global__ void prep_kernel(const float* __restrict__ inp,
                            const float* __restrict__ Wqkv,
                            const float* __restrict__ Wproj,
                            const int* __restrict__ mask)
{
    const int blk = blockIdx.x;
    const int tid = threadIdx.x;

    if (blk < 2048) {                       // X: [S,B,D] fp32 -> [B*S,D] fp16
#pragma unroll
        for (int it = 0; it < 4; ++it) {
            int idx = blk * 1024 + it * 256 + tid;
            int d4 = idx & 255;
            int t  = idx >> 8;
            int b  = t & 3;
            int s  = t >> 2;
            float4 v = *(const float4*)(inp + (((size_t)s * B_ + b) << 10) + d4 * 4);
            __half2* dst = (__half2*)(g_Xh + (((size_t)b * S_ + s) << 10) + d4 * 4);
            dst[0] = __floats2half2_rn(v.x, v.y);
            dst[1] = __floats2half2_rn(v.z, v.w);
        }
    } else if (blk < 2816) {                // Wqkv
#pragma unroll
        for (int it = 0; it < 4; ++it) {
            int idx = (blk - 2048) * 1024 + it * 256 + tid;
            float4 v = *(const float4*)(Wqkv + (size_t)idx * 4);
            __half2* d2 = (__half2*)(g_Wqkvh + (size_t)idx * 4);
            d2[0] = __floats2half2_rn(v.x, v.y);
            d2[1] = __floats2half2_rn(v.z, v.w);
        }
    } else if (blk < 3072) {                // Wproj
#pragma unroll
        for (int it = 0; it < 4; ++it) {
            int idx = (blk - 2816) * 1024 + it * 256 + tid;
            float4 v = *(const float4*)(Wproj + (size_t)idx * 4);
            __half2* d2 = (__half2*)(g_Wprojh + (size_t)idx * 4);
            d2[0] = __floats2half2_rn(v.x, v.y);
            d2[1] = __floats2half2_rn(v.z, v.w);
        }
    } else {                                // key compaction, 1 block / batch
        __shared__ int wsum[8];
        const int b = blk - 3072;
        const int lane = tid & 31, w = tid >> 5;
        const int base = tid * 8;
        int m[8], cnt = 0;
#pragma unroll
        for (int i = 0; i < 8; ++i) {
            m[i] = (mask[(size_t)b * S_ + base + i] == 0);
            cnt += m[i];
        }
        int pre = cnt;
#pragma unroll
        for (int o = 1; o < 32; o <<= 1) {
            int v = __shfl_up_sync(0xffffffffu, pre, o);
            if (lane >= o) pre += v;
        }
        if (lane == 31) wsum[w] = pre;
        __syncthreads();
        if (tid < 8) {
            int v = wsum[tid];
#pragma unroll
            for (int o = 1; o < 8; o <<= 1) {
                int u = __shfl_up_sync(0xffu, v, o);
                if (tid >= o) v += u;
            }
            wsum[tid] = v;
        }
        __syncthreads();
        int excl = pre - cnt + (w > 0 ? wsum[w - 1] : 0);
#pragma unroll
        for (int i = 0; i < 8; ++i)
            if (m[i]) g_kidx[(size_t)b * S_ + excl++] = base + i;
        if (tid == 255) g_kcnt[b] = excl;
    }
}

// ============================================================================
// GEMMs: 128 threads, 4 warps 2x2, warp tile 64x64, BK=64 (stride-72 stages),
// 3-stage cp.async, fp32 accumulate. Half the barriers of the BK=32 version.
// ============================================================================
constexpr int GSTG = 3;
constexpr int GOP_STAGE = 128 * 72;                         // halfs per operand stage
constexpr size_t GEMM_SMEM_BYTES = (size_t)GSTG * 2 * GOP_STAGE * 2;  // 110.6 KB

// QKV GEMM, mask-aware. grid (24, 64). bn<1024: Q mode; else K/V compacted.
__global__ __launch_bounds__(128, 2) void gemm_qkv(const float* __restrict__ bias)
{
    extern __shared__ __half gsm[];

    const int tid = threadIdx.x, lane = tid & 31, warp = tid >> 5;
    const int lq = lane >> 2, lr = lane & 3;
    const int bn = blockIdx.x * 128;
    const bool QMODE = bn < 1024;
    const int m0w = (warp >> 1) * 64, n0w = (warp & 1) * 64;

    int bbat = 0, j0 = 0, cnt = 0, bm = 0;
    if (QMODE) {
        bm = blockIdx.y * 128;
    } else {
        bbat = blockIdx.y >> 4;
        j0 = (blockIdx.y & 15) * 128;
        cnt = g_kcnt[bbat];
        if (j0 >= cnt) return;
    }

    // per-thread load map: 8 (row,chunk) pairs per operand per stage
    const int lrow = tid >> 3, lch = (tid & 7) * 8;   // base row, chunk halfs
    const __half* arow[8];
    const __half* wrow[8];
#pragma unroll
    for (int it = 0; it < 8; ++it) {
        int row = lrow + it * 16;
        if (QMODE) {
            arow[it] = g_Xh + (size_t)(bm + row) * D_ + lch;
        } else {
            int j = j0 + row;
            int src = (j < cnt) ? g_kidx[(size_t)bbat * S_ + j]
                                : g_kidx[(size_t)bbat * S_];
            arow[it] = g_Xh + ((size_t)bbat * S_ + src) * D_ + lch;
        }
        wrow[it] = g_Wqkvh + (size_t)(bn + row) * D_ + lch;
    }

    float acc[4][8][4];
#pragma unroll
    for (int mt = 0; mt < 4; ++mt)
#pragma unroll
        for (int nt = 0; nt < 8; ++nt)
#pragma unroll
            for (int i = 0; i < 4; ++i) acc[mt][nt][i] = 0.f;

    auto issue = [&](int kt) {
        const int k0 = kt * 64;
        const int st = kt % GSTG;
        __half* Asb = gsm + st * 2 * GOP_STAGE;
        __half* Bsb = Asb + GOP_STAGE;
#pragma unroll
        for (int it = 0; it < 8; ++it) {
            int row = lrow + it * 16;
            cpa16(s2u(Asb + row * 72 + lch), arow[it] + k0);
            cpa16(s2u(Bsb + row * 72 + lch), wrow[it] + k0);
        }
    };

    constexpr int NT = D_ / 64;   // 16
    issue(0); cpcommit();
    issue(1); cpcommit();

#pragma unroll 1
    for (int kt = 0; kt < NT; ++kt) {
        if (kt < NT - 1) cpwait<1>(); else cpwait<0>();
        __syncthreads();
        if (kt + 2 < NT) { issue(kt + 2); cpcommit(); }

        const __half* Asb = gsm + (kt % GSTG) * 2 * GOP_STAGE;
        const __half* Bsb = Asb + GOP_STAGE;

#pragma unroll
        for (int kp = 0; kp < 2; ++kp) {
            unsigned af[2][4][4], bf[2][8][2];
#pragma unroll
            for (int ks = 0; ks < 2; ++ks) {
                const int kcol = kp * 32 + ks * 16;
                const int acol = kcol + (lane >> 4) * 8;
#pragma unroll
                for (int mt = 0; mt < 4; ++mt) {
                    int row = m0w + mt * 16 + (lane & 15);
                    ldm4(af[ks][mt][0], af[ks][mt][1], af[ks][mt][2], af[ks][mt][3],
                         s2u(Asb + row * 72 + acol));
                }
#pragma unroll
                for (int ng = 0; ng < 4; ++ng) {
                    int row = n0w + ng * 16 + (lane & 7) + ((lane >> 4) << 3);
                    int col = kcol + (((lane >> 3) & 1) << 3);
                    unsigned r0, r1, r2, r3;
                    ldm4(r0, r1, r2, r3, s2u(Bsb + row * 72 + col));
                    bf[ks][ng * 2][0] = r0; bf[ks][ng * 2][1] = r1;
                    bf[ks][ng * 2 + 1][0] = r2; bf[ks][ng * 2 + 1][1] = r3;
                }
            }
#pragma unroll
            for (int ks = 0; ks < 2; ++ks)
#pragma unroll
                for (int mt = 0; mt < 4; ++mt)
#pragma unroll
                    for (int nt = 0; nt < 8; ++nt)
                        mma16(acc[mt][nt], af[ks][mt], bf[ks][nt]);
        }
    }

    // epilogue
#pragma unroll
    for (int mt = 0; mt < 4; ++mt) {
        int rr0 = m0w + mt * 16 + lq;
        int rr1 = rr0 + 8;
#pragma unroll
        for (int nt = 0; nt < 8; ++nt) {
            int c = bn + n0w + nt * 8 + 2 * lr;
            float b0 = bias[c], b1 = bias[c + 1];
            float v00 = acc[mt][nt][0] + b0, v01 = acc[mt][nt][1] + b1;
            float v10 = acc[mt][nt][2] + b0, v11 = acc[mt][nt][3] + b1;
            if (QMODE) {
                int head = c >> 6, dh = c & 63;
                int m0g = bm + rr0, m1g = bm + rr1;
                int b0i = m0g >> 11, s0 = m0g & (S_ - 1);
                int b1i = m1g >> 11, s1 = m1g & (S_ - 1);
                *(__half2*)(g_Qh + (((size_t)b0i * H_ + head) * S_ + s0) * DH_ + dh) =
                    __floats2half2_rn(v00 * SCALE_F, v01 * SCALE_F);
                *(__half2*)(g_Qh + (((size_t)b1i * H_ + head) * S_ + s1) * DH_ + dh) =
                    __floats2half2_rn(v10 * SCALE_F, v11 * SCALE_F);
            } else {
                int n2 = c - 1024;
                int which = n2 >> 10, nn = n2 & (D_ - 1);
                int head = nn >> 6, dh = nn & 63;
                __half* base = (which == 0 ? g_Kh : g_Vh)
                               + ((size_t)bbat * H_ + head) * S_ * DH_ + dh;
                int jr0 = j0 + rr0, jr1 = j0 + rr1;
                if (jr0 < cnt)
                    *(__half2*)(base + (size_t)jr0 * DH_) = __floats2half2_rn(v00, v01);
                if (jr1 < cnt)
                    *(__half2*)(base + (size_t)jr1 * DH_) = __floats2half2_rn(v10, v11);
            }
        }
    }
}

// Projection GEMM: out = g_attnh @ Wproj^T + b  (BK=64, same structure)
__global__ __launch_bounds__(128, 2) void gemm_proj(
    const float* __restrict__ bias, float* __restrict__ outp)
{
    extern __shared__ __half gsm[];

    const int tid = threadIdx.x, lane = tid & 31, warp = tid >> 5;
    const int lq = lane >> 2, lr = lane & 3;
    const int bm = blockIdx.y * 128, bn = blockIdx.x * 128;
    const int m0w = (warp >> 1) * 64, n0w = (warp & 1) * 64;
    const int lrow = tid >> 3, lch = (tid & 7) * 8;

    float acc[4][8][4];
#pragma unroll
    for (int mt = 0; mt < 4; ++mt)
#pragma unroll
        for (int nt = 0; nt < 8; ++nt)
#pragma unroll
            for (int i = 0; i < 4; ++i) acc[mt][nt][i] = 0.f;

    auto issue = [&](int kt) {
        const int k0 = kt * 64;
        const int st = kt % GSTG;
        __half* Asb = gsm + st * 2 * GOP_STAGE;
        __half* Bsb = Asb + GOP_STAGE;
#pragma unroll
        for (int it = 0; it < 8; ++it) {
            int row = lrow + it * 16;
            cpa16(s2u(Asb + row * 72 + lch),
                  g_attnh + (size_t)(bm + row) * D_ + k0 + lch);
            cpa16(s2u(Bsb + row * 72 + lch),
                  g_Wprojh + (size_t)(bn + row) * D_ + k0 + lch);
        }
    };

    constexpr int NT = D_ / 64;   // 16
    issue(0); cpcommit();
    issue(1); cpcommit();

#pragma unroll 1
    for (int kt = 0; kt < NT; ++kt) {
        if (kt < NT - 1) cpwait<1>(); else cpwait<0>();
        __syncthreads();
        if (kt + 2 < NT) { issue(kt + 2); cpcommit(); }

        const __half* Asb = gsm + (kt % GSTG) * 2 * GOP_STAGE;
        const __half* Bsb = Asb + GOP_STAGE;

#pragma unroll
        for (int kp = 0; kp < 2; ++kp) {
            unsigned af[2][4][4], bf[2][8][2];
#pragma unroll
            for (int ks = 0; ks < 2; ++ks) {
                const int kcol = kp * 32 + ks * 16;
                const int acol = kcol + (lane >> 4) * 8;
#pragma unroll
                for (int mt = 0; mt < 4; ++mt) {
                    int row = m0w + mt * 16 + (lane & 15);
                    ldm4(af[ks][mt][0], af[ks][mt][1], af[ks][mt][2], af[ks][mt][3],
                         s2u(Asb + row * 72 + acol));
                }
#pragma unroll
                for (int ng = 0; ng < 4; ++ng) {
                    int row = n0w + ng * 16 + (lane & 7) + ((lane >> 4) << 3);
                    int col = kcol + (((lane >> 3) & 1) << 3);
                    unsigned r0, r1, r2, r3;
                    ldm4(r0, r1, r2, r3, s2u(Bsb + row * 72 + col));
                    bf[ks][ng * 2][0] = r0; bf[ks][ng * 2][1] = r1;
                    bf[ks][ng * 2 + 1][0] = r2; bf[ks][ng * 2 + 1][1] = r3;
                }
            }
#pragma unroll
            for (int ks = 0; ks < 2; ++ks)
#pragma unroll
                for (int mt = 0; mt < 4; ++mt)
#pragma unroll
                    for (int nt = 0; nt < 8; ++nt)
                        mma16(acc[mt][nt], af[ks][mt], bf[ks][nt]);
        }
    }

#pragma unroll
    for (int mt = 0; mt < 4; ++mt) {
        int r0 = bm + m0w + mt * 16 + lq;
        int r1 = r0 + 8;
        int s0 = r0 & (S_ - 1), bb0 = r0 >> 11;
        int s1 = r1 & (S_ - 1), bb1 = r1 >> 11;
#pragma unroll
        for (int nt = 0; nt < 8; ++nt) {
            int c = bn + n0w + nt * 8 + 2 * lr;
            float b0 = bias[c], b1 = bias[c + 1];
            *(float2*)(outp + ((size_t)s0 * B_ + bb0) * D_ + c) =
                make_float2(acc[mt][nt][0] + b0, acc[mt][nt][1] + b1);
            *(float2*)(outp + ((size_t)s1 * B_ + bb1) * D_ + c) =
                make_float2(acc[mt][nt][2] + b0, acc[mt][nt][3] + b1);
        }
    }
}

// ============================================================================
// Flash attention (R13: 128 q-rows, 8 warps x 16 rows, P in registers,
// 4-stage KV cp.async with uniform one-commit-per-iteration protocol).
// ============================================================================
constexpr int AST = 72;
constexpr int KV_STAGE = 64 * AST;
constexpr int ASTG = 4;
constexpr size_t ATTN_SMEM_BYTES =
    (size_t)(128 * AST + ASTG * 2 * KV_STAGE) * 2;   // 92.2 KB

__global__ __launch_bounds__(256, 2) void attn_h()
{
    extern __shared__ __half smh[];
    __half* Qs = smh;                       // 128 x 72
    __half* Ks = smh + 128 * AST;           // 4 x 64 x 72
    __half* Vs = Ks + ASTG * KV_STAGE;      // 4 x 64 x 72

    const int tid = threadIdx.x, lane = tid & 31, warp = tid >> 5;
    const int lq = lane >> 2, lr = lane & 3;
    const int qt = blockIdx.x, h = blockIdx.y, b = blockIdx.z;
    const int m0 = warp * 16;

    const int cnt = g_kcnt[b];
    const int NTb = (cnt + 63) >> 6 > 0 ? (cnt + 63) >> 6 : 1;

    const __half* Qg = g_Qh + (((size_t)b * H_ + h) * S_ + (size_t)qt * 128) * DH_;
    const __half* Kg = g_Kh + ((size_t)b * H_ + h) * S_ * DH_;
    const __half* Vg = g_Vh + ((size_t)b * H_ + h) * S_ * DH_;

    auto issueKV = [&](int kt) {
        const int st = kt & (ASTG - 1);
#pragma unroll
        for (int it = 0; it < 2; ++it) {
            int c = tid + it * 256;
            int row = c >> 3, ch = (c & 7) * 8;
            size_t g = (size_t)(kt * 64 + row) * DH_ + ch;
            cpa16(s2u(Ks + st * KV_STAGE + row * AST + ch), Kg + g);
            cpa16(s2u(Vs + st * KV_STAGE + row * AST + ch), Vg + g);
        }
    };

#pragma unroll
    for (int it = 0; it < 4; ++it) {
        int c = tid + it * 256;
        int row = c >> 3, ch = (c & 7) * 8;
        cpa16(s2u(Qs + row * AST + ch), Qg + (size_t)row * DH_ + ch);
    }
    issueKV(0); cpcommit();
    issueKV(1); cpcommit();
    issueKV(2); cpcommit();

    float oacc[8][4];
#pragma unroll
    for (int nt = 0; nt < 8; ++nt)
#pragma unroll
        for (int i = 0; i < 4; ++i) oacc[nt][i] = 0.f;
    float l0_ = 0.f, l1_ = 0.f;

#pragma unroll 1
    for (int kt = 0; kt < NTb; ++kt) {
        cpwait<2>();
        __syncthreads();
        if (kt + 3 < NTb) issueKV(kt + 3);
        cpcommit();               // exactly one commit per iteration (may be empty)

        const __half* Kb = Ks + (kt & (ASTG - 1)) * KV_STAGE;
        const __half* Vb = Vs + (kt & (ASTG - 1)) * KV_STAGE;
        const int jbase = kt * 64;

        // ---- S = Q K^T ----
        float sacc[8][4];
#pragma unroll
        for (int nt = 0; nt < 8; ++nt)
#pragma unroll
            for (int i = 0; i < 4; ++i) sacc[nt][i] = 0.f;
#pragma unroll
        for (int ks = 0; ks < 4; ++ks) {
            unsigned qa[4];
            {
                int row = m0 + (lane & 15);
                int col = ks * 16 + (lane >> 4) * 8;
                ldm4(qa[0], qa[1], qa[2], qa[3], s2u(Qs + row * AST + col));
            }
            unsigned bf[8][2];
#pragma unroll
            for (int ng = 0; ng < 4; ++ng) {
                int row = ng * 16 + (lane & 7) + ((lane >> 4) << 3);
                int col = ks * 16 + (((lane >> 3) & 1) << 3);
                unsigned r0, r1, r2, r3;
                ldm4(r0, r1, r2, r3, s2u(Kb + row * AST + col));
                bf[ng * 2][0] = r0; bf[ng * 2][1] = r1;
                bf[ng * 2 + 1][0] = r2; bf[ng * 2 + 1][1] = r3;
            }
#pragma unroll
            for (int nt = 0; nt < 8; ++nt)
                mma16(sacc[nt], qa, bf[nt]);
        }

        // ---- exp -> P fragments in registers ----
        unsigned pp[8][2];
        if (jbase + 64 <= cnt) {
#pragma unroll
            for (int nt = 0; nt < 8; ++nt) {
                float p00 = __expf(sacc[nt][0]);
                float p01 = __expf(sacc[nt][1]);
                float p10 = __expf(sacc[nt][2]);
                float p11 = __expf(sacc[nt][3]);
                l0_ += p00 + p01; l1_ += p10 + p11;
                __half2 h0 = __floats2half2_rn(p00, p01);
                __half2 h1 = __floats2half2_rn(p10, p11);
                pp[nt][0] = *(unsigned*)&h0;
                pp[nt][1] = *(unsigned*)&h1;
            }
        } else {
#pragma unroll
            for (int nt = 0; nt < 8; ++nt) {
                int c = nt * 8 + 2 * lr;
                bool k0v = (jbase + c) < cnt, k1v = (jbase + c + 1) < cnt;
                float p00 = k0v ? __expf(sacc[nt][0]) : 0.f;
                float p01 = k1v ? __expf(sacc[nt][1]) : 0.f;
                float p10 = k0v ? __expf(sacc[nt][2]) : 0.f;
                float p11 = k1v ? __expf(sacc[nt][3]) : 0.f;
                l0_ += p00 + p01; l1_ += p10 + p11;
                __half2 h0 = __floats2half2_rn(p00, p01);
                __half2 h1 = __floats2half2_rn(p10, p11);
                pp[nt][0] = *(unsigned*)&h0;
                pp[nt][1] = *(unsigned*)&h1;
            }
        }

        // ---- O += P V ----
#pragma unroll
        for (int ks = 0; ks < 4; ++ks) {
            unsigned pa[4] = {pp[2 * ks][0], pp[2 * ks][1],
                              pp[2 * ks + 1][0], pp[2 * ks + 1][1]};
            unsigned bf[8][2];
#pragma unroll
            for (int ng = 0; ng < 4; ++ng) {
                int row = ks * 16 + (lane & 7) + (((lane >> 3) & 1) << 3);
                int col = ng * 16 + (lane >> 4) * 8;
                unsigned r0, r1, r2, r3;
                ldm4t(r0, r1, r2, r3, s2u(Vb + row * AST + col));
                bf[ng * 2][0] = r0; bf[ng * 2][1] = r1;
                bf[ng * 2 + 1][0] = r2; bf[ng * 2 + 1][1] = r3;
            }
#pragma unroll
            for (int nt = 0; nt < 8; ++nt)
                mma16(oacc[nt], pa, bf[nt]);
        }
    }

    // reduce l over the lr quad
    l0_ += __shfl_xor_sync(0xffffffffu, l0_, 1);
    l0_ += __shfl_xor_sync(0xffffffffu, l0_, 2);
    l1_ += __shfl_xor_sync(0xffffffffu, l1_, 1);
    l1_ += __shfl_xor_sync(0xffffffffu, l1_, 2);

    float inv0 = (l0_ > 0.f) ? 1.f / l0_ : 0.f;
    float inv1 = (l1_ > 0.f) ? 1.f / l1_ : 0.f;
    int q0 = qt * 128 + m0 + lq;
    int q1 = q0 + 8;
    __half* O0 = g_attnh + ((size_t)b * S_ + q0) * D_ + h * DH_;
    __half* O1 = g_attnh + ((size_t)b * S_ + q1) * D_ + h * DH_;
#pragma unroll
    for (int nt = 0; nt < 8; ++nt) {
        int c = nt * 8 + 2 * lr;
        *(__half2*)(O0 + c) = __floats2half2_rn(oacc[nt][0] * inv0, oacc[nt][1] * inv0);
        *(__half2*)(O1 + c) = __floats2half2_rn(oacc[nt][2] * inv1, oacc[nt][3] * inv1);
    }
}

// ============================================================================
extern "C" void kernel_launch(void* const* d_in, const int* in_sizes, int n_in,
                              void* d_out, int out_size)
{
    (void)in_sizes; (void)n_in; (void)out_size;
    const float* inp   = (const float*)d_in[0];   // [S,B,D]
    const int*   amask = (const int*)d_in[1];     // [B,S]
    const float* Wqkv  = (const float*)d_in[2];   // [3D,D]
    const float* bqkv  = (const float*)d_in[3];   // [3D]
    const float* Wproj = (const float*)d_in[4];   // [D,D]
    const float* bproj = (const float*)d_in[5];   // [D]
    float* out = (float*)d_out;                   // [S,B,D]

    cudaFuncSetAttribute(gemm_qkv, cudaFuncAttributeMaxDynamicSharedMemorySize,
                         (int)GEMM_SMEM_BYTES);
    cudaFuncSetAttribute(gemm_proj, cudaFuncAttributeMaxDynamicSharedMemorySize,
                         (int)GEMM_SMEM_BYTES);
    cudaFuncSetAttribute(attn_h, cudaFuncAttributeMaxDynamicSharedMemorySize,
                         (int)ATTN_SMEM_BYTES);

    prep_kernel<<<3076, 256>>>(inp, Wqkv, Wproj, amask);
    gemm_qkv<<<dim3(24, 64), 128, GEMM_SMEM_BYTES>>>(bqkv);
    attn_h<<<dim3(S_ / 128, H_, B_), 256, ATTN_SMEM_BYTES>>>();
    gemm_proj<<<dim3(8, 64), 128, GEMM_SMEM_BYTES>>>(bproj, out);
}

// round 15
// speedup vs baseline: 1.0274x; 1.0274x over previous
#include <cuda_runtime.h>
#include <cuda_fp16.h>
#include <cstdint>

constexpr int S_  = 2048;
constexpr int B_  = 4;
constexpr int D_  = 1024;
constexpr int H_  = 16;
constexpr int DH_ = 64;
#define SCALE_F 0.125f              // 1/sqrt(64)
#define SCALE_LOG2E 0.18033688f     // SCALE * log2(e); exp(s*SCALE) = exp2(s*this)

// ---------------- fp16 scratch (device globals) -----------------------------
__device__ __half g_Xh[(size_t)B_ * S_ * D_];        // [B*S, D]  (m = b*S+s)
__device__ __half g_Wqkvh[(size_t)3 * D_ * D_];      // [3D, D]
__device__ __half g_Wprojh[(size_t)D_ * D_];         // [D, D]
__device__ __half g_Qh[(size_t)B_ * H_ * S_ * DH_];  // [B,H,S,DH] (pre-scaled by SCALE*log2e)
__device__ __half g_Kh[(size_t)B_ * H_ * S_ * DH_];  // [B,H,j,DH] compacted
__device__ __half g_Vh[(size_t)B_ * H_ * S_ * DH_];  // [B,H,j,DH] compacted
__device__ __half g_attnh[(size_t)B_ * S_ * D_];     // [B*S, D]
__device__ int    g_kidx[(size_t)B_ * S_];           // compacted key indices
__device__ int    g_kcnt[B_];                        // kept-key counts

// ---------------- asm helpers ------------------------------------------------
__device__ __forceinline__ uint32_t s2u(const void* p) {
    return (uint32_t)__cvta_generic_to_shared(p);
}
__device__ __forceinline__ void cpa16(uint32_t d, const void* s) {
    asm volatile("cp.async.cg.shared.global [%0], [%1], 16;\n" :: "r"(d), "l"(s));
}
__device__ __forceinline__ void cpcommit() {
    asm volatile("cp.async.commit_group;\n");
}
template <int N> __device__ __forceinline__ void cpwait() {
    asm volatile("cp.async.wait_group %0;\n" :: "n"(N));
}
__device__ __forceinline__ void ldm4(unsigned& r0, unsigned& r1, unsigned& r2,
                                     unsigned& r3, uint32_t a) {
    asm volatile("ldmatrix.sync.aligned.m8n8.x4.shared.b16 {%0,%1,%2,%3},[%4];"
                 : "=r"(r0), "=r"(r1), "=r"(r2), "=r"(r3) : "r"(a));
}
__device__ __forceinline__ void ldm4t(unsigned& r0, unsigned& r1, unsigned& r2,
                                      unsigned& r3, uint32_t a) {
    asm volatile("ldmatrix.sync.aligned.m8n8.x4.trans.shared.b16 {%0,%1,%2,%3},[%4];"
                 : "=r"(r0), "=r"(r1), "=r"(r2), "=r"(r3) : "r"(a));
}
__device__ __forceinline__ void mma16(float* c, const unsigned* a, const unsigned* b) {
    asm volatile(
        "mma.sync.aligned.m16n8k16.row.col.f32.f16.f16.f32 "
        "{%0,%1,%2,%3},{%4,%5,%6,%7},{%8,%9},{%0,%1,%2,%3};"
        : "+f"(c[0]), "+f"(c[1]), "+f"(c[2]), "+f"(c[3])
        : "r"(a[0]), "r"(a[1]), "r"(a[2]), "r"(a[3]), "r"(b[0]), "r"(b[1]));
}
__device__ __forceinline__ float ex2(float x) {
    float r;
    asm("ex2.approx.f32 %0, %1;" : "=f"(r) : "f"(x));
    return r;
}

// ============================================================================
// Fused prep: X/W conversions (4 float4 per thread) + key compaction.
// ============================================================================
__global__ void prep_kernel(const float* __restrict__ inp,
                            const float* __restrict__ Wqkv,
                            const float* __restrict__ Wproj,
                            const int* __restrict__ mask)
{
    const int blk = blockIdx.x;
    const int tid = threadIdx.x;

    if (blk < 2048) {                       // X: [S,B,D] fp32 -> [B*S,D] fp16
#pragma unroll
        for (int it = 0; it < 4; ++it) {
            int idx = blk * 1024 + it * 256 + tid;
            int d4 = idx & 255;
            int t  = idx >> 8;
            int b  = t & 3;
            int s  = t >> 2;
            float4 v = *(const float4*)(inp + (((size_t)s * B_ + b) << 10) + d4 * 4);
            __half2* dst = (__half2*)(g_Xh + (((size_t)b * S_ + s) << 10) + d4 * 4);
            dst[0] = __floats2half2_rn(v.x, v.y);
            dst[1] = __floats2half2_rn(v.z, v.w);
        }
    } else if (blk < 2816) {                // Wqkv
#pragma unroll
        for (int it = 0; it < 4; ++it) {
            int idx = (blk - 2048) * 1024 + it * 256 + tid;
            float4 v = *(const float4*)(Wqkv + (size_t)idx * 4);
            __half2* d2 = (__half2*)(g_Wqkvh + (size_t)idx * 4);
            d2[0] = __floats2half2_rn(v.x, v.y);
            d2[1] = __floats2half2_rn(v.z, v.w);
        }
    } else if (blk < 3072) {                // Wproj
#pragma unroll
        for (int it = 0; it < 4; ++it) {
            int idx = (blk - 2816) * 1024 + it * 256 + tid;
            float4 v = *(const float4*)(Wproj + (size_t)idx * 4);
            __half2* d2 = (__half2*)(g_Wprojh + (size_t)idx * 4);
            d2[0] = __floats2half2_rn(v.x, v.y);
            d2[1] = __floats2half2_rn(v.z, v.w);
        }
    } else {                                // key compaction, 1 block / batch
        __shared__ int wsum[8];
        const int b = blk - 3072;
        const int lane = tid & 31, w = tid >> 5;
        const int base = tid * 8;
        int m[8], cnt = 0;
#pragma unroll
        for (int i = 0; i < 8; ++i) {
            m[i] = (mask[(size_t)b * S_ + base + i] == 0);
            cnt += m[i];
        }
        int pre = cnt;
#pragma unroll
        for (int o = 1; o < 32; o <<= 1) {
            int v = __shfl_up_sync(0xffffffffu, pre, o);
            if (lane >= o) pre += v;
        }
        if (lane == 31) wsum[w] = pre;
        __syncthreads();
        if (tid < 8) {
            int v = wsum[tid];
#pragma unroll
            for (int o = 1; o < 8; o <<= 1) {
                int u = __shfl_up_sync(0xffu, v, o);
                if (tid >= o) v += u;
            }
            wsum[tid] = v;
        }
        __syncthreads();
        int excl = pre - cnt + (w > 0 ? wsum[w - 1] : 0);
#pragma unroll
        for (int i = 0; i < 8; ++i)
            if (m[i]) g_kidx[(size_t)b * S_ + excl++] = base + i;
        if (tid == 255) g_kcnt[b] = excl;
    }
}

// ============================================================================
// GEMMs (R13/R11 config: 128 threads, 4 warps 2x2, warp tile 64x64,
// BK=32, 4-stage cp.async, fp32 accumulate, all-fragments-first).
// ============================================================================
constexpr int GSTG = 4;
constexpr int GA_STAGE = 128 * 40;
constexpr size_t GEMM_SMEM_BYTES = (size_t)2 * GSTG * GA_STAGE * 2;   // 80 KB

// QKV GEMM, mask-aware. grid (24, 64). bn<1024: Q mode; else K/V compacted.
__global__ __launch_bounds__(128, 2) void gemm_qkv(const float* __restrict__ bias)
{
    extern __shared__ __half gsm[];
    __half* Asm = gsm;
    __half* Bsm = gsm + GSTG * GA_STAGE;

    const int tid = threadIdx.x, lane = tid & 31, warp = tid >> 5;
    const int lq = lane >> 2, lr = lane & 3;
    const int bn = blockIdx.x * 128;
    const bool QMODE = bn < 1024;
    const int m0w = (warp >> 1) * 64, n0w = (warp & 1) * 64;
    const int crow = tid >> 2, cch = (tid & 3) * 8;

    int bbat = 0, j0 = 0, cnt = 0, bm = 0;
    if (QMODE) {
        bm = blockIdx.y * 128;
    } else {
        bbat = blockIdx.y >> 4;
        j0 = (blockIdx.y & 15) * 128;
        cnt = g_kcnt[bbat];
        if (j0 >= cnt) return;
    }

    const __half* arow[4];
    const __half* wrow[4];
#pragma unroll
    for (int it = 0; it < 4; ++it) {
        int row = crow + it * 32;
        if (QMODE) {
            arow[it] = g_Xh + (size_t)(bm + row) * D_ + cch;
        } else {
            int j = j0 + row;
            int src = (j < cnt) ? g_kidx[(size_t)bbat * S_ + j]
                                : g_kidx[(size_t)bbat * S_];
            arow[it] = g_Xh + ((size_t)bbat * S_ + src) * D_ + cch;
        }
        wrow[it] = g_Wqkvh + (size_t)(bn + row) * D_ + cch;
    }

    float acc[4][8][4];
#pragma unroll
    for (int mt = 0; mt < 4; ++mt)
#pragma unroll
        for (int nt = 0; nt < 8; ++nt)
#pragma unroll
            for (int i = 0; i < 4; ++i) acc[mt][nt][i] = 0.f;

    auto issue = [&](int kt) {
        const int k0 = kt * 32, st = kt & (GSTG - 1);
        __half* Asb = Asm + st * GA_STAGE;
        __half* Bsb = Bsm + st * GA_STAGE;
#pragma unroll
        for (int it = 0; it < 4; ++it) {
            int row = crow + it * 32;
            cpa16(s2u(Asb + row * 40 + cch), arow[it] + k0);
            cpa16(s2u(Bsb + row * 40 + cch), wrow[it] + k0);
        }
    };

    constexpr int NT = D_ / 32;   // 32
    issue(0); cpcommit();
    issue(1); cpcommit();
    issue(2); cpcommit();

#pragma unroll 1
    for (int kt = 0; kt < NT; ++kt) {
        if (kt < NT - 2) cpwait<2>();
        else if (kt == NT - 2) cpwait<1>();
        else cpwait<0>();
        __syncthreads();
        if (kt + 3 < NT) { issue(kt + 3); cpcommit(); }

        const __half* Asb = Asm + (kt & (GSTG - 1)) * GA_STAGE;
        const __half* Bsb = Bsm + (kt & (GSTG - 1)) * GA_STAGE;

        unsigned af[2][4][4], bf[2][8][2];
#pragma unroll
        for (int ks = 0; ks < 2; ++ks) {
            const int acol = ks * 16 + (lane >> 4) * 8;
#pragma unroll
            for (int mt = 0; mt < 4; ++mt) {
                int row = m0w + mt * 16 + (lane & 15);
                ldm4(af[ks][mt][0], af[ks][mt][1], af[ks][mt][2], af[ks][mt][3],
                     s2u(Asb + row * 40 + acol));
            }
#pragma unroll
            for (int ng = 0; ng < 4; ++ng) {
                int row = n0w + ng * 16 + (lane & 7) + ((lane >> 4) << 3);
                int col = ks * 16 + (((lane >> 3) & 1) << 3);
                unsigned r0, r1, r2, r3;
                ldm4(r0, r1, r2, r3, s2u(Bsb + row * 40 + col));
                bf[ks][ng * 2][0] = r0; bf[ks][ng * 2][1] = r1;
                bf[ks][ng * 2 + 1][0] = r2; bf[ks][ng * 2 + 1][1] = r3;
            }
        }
#pragma unroll
        for (int ks = 0; ks < 2; ++ks)
#pragma unroll
            for (int mt = 0; mt < 4; ++mt)
#pragma unroll
                for (int nt = 0; nt < 8; ++nt)
                    mma16(acc[mt][nt], af[ks][mt], bf[ks][nt]);
    }

    // epilogue
#pragma unroll
    for (int mt = 0; mt < 4; ++mt) {
        int rr0 = m0w + mt * 16 + lq;
        int rr1 = rr0 + 8;
#pragma unroll
        for (int nt = 0; nt < 8; ++nt) {
            int c = bn + n0w + nt * 8 + 2 * lr;
            float b0 = bias[c], b1 = bias[c + 1];
            float v00 = acc[mt][nt][0] + b0, v01 = acc[mt][nt][1] + b1;
            float v10 = acc[mt][nt][2] + b0, v11 = acc[mt][nt][3] + b1;
            if (QMODE) {
                int head = c >> 6, dh = c & 63;
                int m0g = bm + rr0, m1g = bm + rr1;
                int b0i = m0g >> 11, s0 = m0g & (S_ - 1);
                int b1i = m1g >> 11, s1 = m1g & (S_ - 1);
                *(__half2*)(g_Qh + (((size_t)b0i * H_ + head) * S_ + s0) * DH_ + dh) =
                    __floats2half2_rn(v00 * SCALE_LOG2E, v01 * SCALE_LOG2E);
                *(__half2*)(g_Qh + (((size_t)b1i * H_ + head) * S_ + s1) * DH_ + dh) =
                    __floats2half2_rn(v10 * SCALE_LOG2E, v11 * SCALE_LOG2E);
            } else {
                int n2 = c - 1024;
                int which = n2 >> 10, nn = n2 & (D_ - 1);
                int head = nn >> 6, dh = nn & 63;
                __half* base = (which == 0 ? g_Kh : g_Vh)
                               + ((size_t)bbat * H_ + head) * S_ * DH_ + dh;
                int jr0 = j0 + rr0, jr1 = j0 + rr1;
                if (jr0 < cnt)
                    *(__half2*)(base + (size_t)jr0 * DH_) = __floats2half2_rn(v00, v01);
                if (jr1 < cnt)
                    *(__half2*)(base + (size_t)jr1 * DH_) = __floats2half2_rn(v10, v11);
            }
        }
    }
}

// Projection GEMM: out = g_attnh @ Wproj^T + b
__global__ __launch_bounds__(128, 2) void gemm_proj(
    const float* __restrict__ bias, float* __restrict__ outp)
{
    extern __shared__ __half gsm[];
    __half* Asm = gsm;
    __half* Bsm = gsm + GSTG * GA_STAGE;

    const int tid = threadIdx.x, lane = tid & 31, warp = tid >> 5;
    const int lq = lane >> 2, lr = lane & 3;
    const int bm = blockIdx.y * 128, bn = blockIdx.x * 128;
    const int m0w = (warp >> 1) * 64, n0w = (warp & 1) * 64;
    const int crow = tid >> 2, cch = (tid & 3) * 8;

    float acc[4][8][4];
#pragma unroll
    for (int mt = 0; mt < 4; ++mt)
#pragma unroll
        for (int nt = 0; nt < 8; ++nt)
#pragma unroll
            for (int i = 0; i < 4; ++i) acc[mt][nt][i] = 0.f;

    auto issue = [&](int kt) {
        const int k0 = kt * 32, st = kt & (GSTG - 1);
        __half* Asb = Asm + st * GA_STAGE;
        __half* Bsb = Bsm + st * GA_STAGE;
#pragma unroll
        for (int it = 0; it < 4; ++it) {
            int row = crow + it * 32;
            cpa16(s2u(Asb + row * 40 + cch), g_attnh + (size_t)(bm + row) * D_ + k0 + cch);
            cpa16(s2u(Bsb + row * 40 + cch), g_Wprojh + (size_t)(bn + row) * D_ + k0 + cch);
        }
    };

    constexpr int NT = D_ / 32;
    issue(0); cpcommit();
    issue(1); cpcommit();
    issue(2); cpcommit();

#pragma unroll 1
    for (int kt = 0; kt < NT; ++kt) {
        if (kt < NT - 2) cpwait<2>();
        else if (kt == NT - 2) cpwait<1>();
        else cpwait<0>();
        __syncthreads();
        if (kt + 3 < NT) { issue(kt + 3); cpcommit(); }

        const __half* Asb = Asm + (kt & (GSTG - 1)) * GA_STAGE;
        const __half* Bsb = Bsm + (kt & (GSTG - 1)) * GA_STAGE;

        unsigned af[2][4][4], bf[2][8][2];
#pragma unroll
        for (int ks = 0; ks < 2; ++ks) {
            const int acol = ks * 16 + (lane >> 4) * 8;
#pragma unroll
            for (int mt = 0; mt < 4; ++mt) {
                int row = m0w + mt * 16 + (lane & 15);
                ldm4(af[ks][mt][0], af[ks][mt][1], af[ks][mt][2], af[ks][mt][3],
                     s2u(Asb + row * 40 + acol));
            }
#pragma unroll
            for (int ng = 0; ng < 4; ++ng) {
                int row = n0w + ng * 16 + (lane & 7) + ((lane >> 4) << 3);
                int col = ks * 16 + (((lane >> 3) & 1) << 3);
                unsigned r0, r1, r2, r3;
                ldm4(r0, r1, r2, r3, s2u(Bsb + row * 40 + col));
                bf[ks][ng * 2][0] = r0; bf[ks][ng * 2][1] = r1;
                bf[ks][ng * 2 + 1][0] = r2; bf[ks][ng * 2 + 1][1] = r3;
            }
        }
#pragma unroll
        for (int ks = 0; ks < 2; ++ks)
#pragma unroll
            for (int mt = 0; mt < 4; ++mt)
#pragma unroll
                for (int nt = 0; nt < 8; ++nt)
                    mma16(acc[mt][nt], af[ks][mt], bf[ks][nt]);
    }

#pragma unroll
    for (int mt = 0; mt < 4; ++mt) {
        int r0 = bm + m0w + mt * 16 + lq;
        int r1 = r0 + 8;
        int s0 = r0 & (S_ - 1), bb0 = r0 >> 11;
        int s1 = r1 & (S_ - 1), bb1 = r1 >> 11;
#pragma unroll
        for (int nt = 0; nt < 8; ++nt) {
            int c = bn + n0w + nt * 8 + 2 * lr;
            float b0 = bias[c], b1 = bias[c + 1];
            *(float2*)(outp + ((size_t)s0 * B_ + bb0) * D_ + c) =
                make_float2(acc[mt][nt][0] + b0, acc[mt][nt][1] + b1);
            *(float2*)(outp + ((size_t)s1 * B_ + bb1) * D_ + c) =
                make_float2(acc[mt][nt][2] + b0, acc[mt][nt][3] + b1);
        }
    }
}

// ============================================================================
// Flash attention (R13: 128 q-rows, 8 warps x 16 rows, P in registers,
// 4-stage KV cp.async, uniform one-commit-per-iteration). Scores arrive in
// log2 domain (Q pre-scaled by SCALE*log2e) -> plain ex2, no FMUL.
// ============================================================================
constexpr int AST = 72;
constexpr int KV_STAGE = 64 * AST;
constexpr int ASTG = 4;
constexpr size_t ATTN_SMEM_BYTES =
    (size_t)(128 * AST + ASTG * 2 * KV_STAGE) * 2;   // 92.2 KB

__global__ __launch_bounds__(256, 2) void attn_h()
{
    extern __shared__ __half smh[];
    __half* Qs = smh;                       // 128 x 72
    __half* Ks = smh + 128 * AST;           // 4 x 64 x 72
    __half* Vs = Ks + ASTG * KV_STAGE;      // 4 x 64 x 72

    const int tid = threadIdx.x, lane = tid & 31, warp = tid >> 5;
    const int lq = lane >> 2, lr = lane & 3;
    const int qt = blockIdx.x, h = blockIdx.y, b = blockIdx.z;
    const int m0 = warp * 16;

    const int cnt = g_kcnt[b];
    const int NTb = (cnt + 63) >> 6 > 0 ? (cnt + 63) >> 6 : 1;

    const __half* Qg = g_Qh + (((size_t)b * H_ + h) * S_ + (size_t)qt * 128) * DH_;
    const __half* Kg = g_Kh + ((size_t)b * H_ + h) * S_ * DH_;
    const __half* Vg = g_Vh + ((size_t)b * H_ + h) * S_ * DH_;

    auto issueKV = [&](int kt) {
        const int st = kt & (ASTG - 1);
#pragma unroll
        for (int it = 0; it < 2; ++it) {
            int c = tid + it * 256;
            int row = c >> 3, ch = (c & 7) * 8;
            size_t g = (size_t)(kt * 64 + row) * DH_ + ch;
            cpa16(s2u(Ks + st * KV_STAGE + row * AST + ch), Kg + g);
            cpa16(s2u(Vs + st * KV_STAGE + row * AST + ch), Vg + g);
        }
    };

#pragma unroll
    for (int it = 0; it < 4; ++it) {
        int c = tid + it * 256;
        int row = c >> 3, ch = (c & 7) * 8;
        cpa16(s2u(Qs + row * AST + ch), Qg + (size_t)row * DH_ + ch);
    }
    issueKV(0); cpcommit();
    issueKV(1); cpcommit();
    issueKV(2); cpcommit();

    float oacc[8][4];
#pragma unroll
    for (int nt = 0; nt < 8; ++nt)
#pragma unroll
        for (int i = 0; i < 4; ++i) oacc[nt][i] = 0.f;
    float l0_ = 0.f, l1_ = 0.f;

#pragma unroll 1
    for (int kt = 0; kt < NTb; ++kt) {
        cpwait<2>();
        __syncthreads();
        if (kt + 3 < NTb) issueKV(kt + 3);
        cpcommit();               // exactly one commit per iteration (may be empty)

        const __half* Kb = Ks + (kt & (ASTG - 1)) * KV_STAGE;
        const __half* Vb = Vs + (kt & (ASTG - 1)) * KV_STAGE;
        const int jbase = kt * 64;

        // ---- S = Q K^T ----
        float sacc[8][4];
#pragma unroll
        for (int nt = 0; nt < 8; ++nt)
#pragma unroll
            for (int i = 0; i < 4; ++i) sacc[nt][i] = 0.f;
#pragma unroll
        for (int ks = 0; ks < 4; ++ks) {
            unsigned qa[4];
            {
                int row = m0 + (lane & 15);
                int col = ks * 16 + (lane >> 4) * 8;
                ldm4(qa[0], qa[1], qa[2], qa[3], s2u(Qs + row * AST + col));
            }
            unsigned bf[8][2];
#pragma unroll
            for (int ng = 0; ng < 4; ++ng) {
                int row = ng * 16 + (lane & 7) + ((lane >> 4) << 3);
                int col = ks * 16 + (((lane >> 3) & 1) << 3);
                unsigned r0, r1, r2, r3;
                ldm4(r0, r1, r2, r3, s2u(Kb + row * AST + col));
                bf[ng * 2][0] = r0; bf[ng * 2][1] = r1;
                bf[ng * 2 + 1][0] = r2; bf[ng * 2 + 1][1] = r3;
            }
#pragma unroll
            for (int nt = 0; nt < 8; ++nt)
                mma16(sacc[nt], qa, bf[nt]);
        }

        // ---- ex2 -> P fragments in registers (scores already in log2 domain)
        unsigned pp[8][2];
        if (jbase + 64 <= cnt) {
#pragma unroll
            for (int nt = 0; nt < 8; ++nt) {
                float p00 = ex2(sacc[nt][0]);
                float p01 = ex2(sacc[nt][1]);
                float p10 = ex2(sacc[nt][2]);
                float p11 = ex2(sacc[nt][3]);
                l0_ += p00 + p01; l1_ += p10 + p11;
                __half2 h0 = __floats2half2_rn(p00, p01);
                __half2 h1 = __floats2half2_rn(p10, p11);
                pp[nt][0] = *(unsigned*)&h0;
                pp[nt][1] = *(unsigned*)&h1;
            }
        } else {
#pragma unroll
            for (int nt = 0; nt < 8; ++nt) {
                int c = nt * 8 + 2 * lr;
                bool k0v = (jbase + c) < cnt, k1v = (jbase + c + 1) < cnt;
                float p00 = k0v ? ex2(sacc[nt][0]) : 0.f;
                float p01 = k1v ? ex2(sacc[nt][1]) : 0.f;
                float p10 = k0v ? ex2(sacc[nt][2]) : 0.f;
                float p11 = k1v ? ex2(sacc[nt][3]) : 0.f;
                l0_ += p00 + p01; l1_ += p10 + p11;
                __half2 h0 = __floats2half2_rn(p00, p01);
                __half2 h1 = __floats2half2_rn(p10, p11);
                pp[nt][0] = *(unsigned*)&h0;
                pp[nt][1] = *(unsigned*)&h1;
            }
        }

        // ---- O += P V  (P from registers) ----
#pragma unroll
        for (int ks = 0; ks < 4; ++ks) {
            unsigned pa[4] = {pp[2 * ks][0], pp[2 * ks][1],
                              pp[2 * ks + 1][0], pp[2 * ks + 1][1]};
            unsigned bf[8][2];
#pragma unroll
            for (int ng = 0; ng < 4; ++ng) {
                int row = ks * 16 + (lane & 7) + (((lane >> 3) & 1) << 3);
                int col = ng * 16 + (lane >> 4) * 8;
                unsigned r0, r1, r2, r3;
                ldm4t(r0, r1, r2, r3, s2u(Vb + row * AST + col));
                bf[ng * 2][0] = r0; bf[ng * 2][1] = r1;
                bf[ng * 2 + 1][0] = r2; bf[ng * 2 + 1][1] = r3;
            }
#pragma unroll
            for (int nt = 0; nt < 8; ++nt)
                mma16(oacc[nt], pa, bf[nt]);
        }
    }

    // reduce l over the lr quad
    l0_ += __shfl_xor_sync(0xffffffffu, l0_, 1);
    l0_ += __shfl_xor_sync(0xffffffffu, l0_, 2);
    l1_ += __shfl_xor_sync(0xffffffffu, l1_, 1);
    l1_ += __shfl_xor_sync(0xffffffffu, l1_, 2);

    float inv0 = (l0_ > 0.f) ? 1.f / l0_ : 0.f;
    float inv1 = (l1_ > 0.f) ? 1.f / l1_ : 0.f;
    int q0 = qt * 128 + m0 + lq;
    int q1 = q0 + 8;
    __half* O0 = g_attnh + ((size_t)b * S_ + q0) * D_ + h * DH_;
    __half* O1 = g_attnh + ((size_t)b * S_ + q1) * D_ + h * DH_;
#pragma unroll
    for (int nt = 0; nt < 8; ++nt) {
        int c = nt * 8 + 2 * lr;
        *(__half2*)(O0 + c) = __floats2half2_rn(oacc[nt][0] * inv0, oacc[nt][1] * inv0);
        *(__half2*)(O1 + c) = __floats2half2_rn(oacc[nt][2] * inv1, oacc[nt][3] * inv1);
    }
}

// ============================================================================
extern "C" void kernel_launch(void* const* d_in, const int* in_sizes, int n_in,
                              void* d_out, int out_size)
{
    (void)in_sizes; (void)n_in; (void)out_size;
    const float* inp   = (const float*)d_in[0];   // [S,B,D]
    const int*   amask = (const int*)d_in[1];     // [B,S]
    const float* Wqkv  = (const float*)d_in[2];   // [3D,D]
    const float* bqkv  = (const float*)d_in[3];   // [3D]
    const float* Wproj = (const float*)d_in[4];   // [D,D]
    const float* bproj = (const float*)d_in[5];   // [D]
    float* out = (float*)d_out;                   // [S,B,D]

    cudaFuncSetAttribute(gemm_qkv, cudaFuncAttributeMaxDynamicSharedMemorySize,
                         (int)GEMM_SMEM_BYTES);
    cudaFuncSetAttribute(gemm_proj, cudaFuncAttributeMaxDynamicSharedMemorySize,
                         (int)GEMM_SMEM_BYTES);
    cudaFuncSetAttribute(attn_h, cudaFuncAttributeMaxDynamicSharedMemorySize,
                         (int)ATTN_SMEM_BYTES);

    prep_kernel<<<3076, 256>>>(inp, Wqkv, Wproj, amask);
    gemm_qkv<<<dim3(24, 64), 128, GEMM_SMEM_BYTES>>>(bqkv);
    attn_h<<<dim3(S_ / 128, H_, B_), 256, ATTN_SMEM_BYTES>>>();
    gemm_proj<<<dim3(8, 64), 128, GEMM_SMEM_BYTES>>>(bproj, out);
}

// round 16
// speedup vs baseline: 1.0329x; 1.0054x over previous
#include <cuda_runtime.h>
#include <cuda_fp16.h>
#include <cstdint>

constexpr int S_  = 2048;
constexpr int B_  = 4;
constexpr int D_  = 1024;
constexpr int H_  = 16;
constexpr int DH_ = 64;
#define SCALE_F 0.125f   // 1/sqrt(64)

// ---------------- fp16 scratch (device globals) -----------------------------
__device__ __half g_Xh[(size_t)B_ * S_ * D_];        // [B*S, D]  (m = b*S+s)
__device__ __half g_Wqkvh[(size_t)3 * D_ * D_];      // [3D, D]
__device__ __half g_Wprojh[(size_t)D_ * D_];         // [D, D]
__device__ __half g_Qh[(size_t)B_ * H_ * S_ * DH_];  // [B,H,S,DH]   (pre-scaled)
__device__ __half g_Kh[(size_t)B_ * H_ * S_ * DH_];  // [B,H,j,DH]   compacted
__device__ __half g_Vh[(size_t)B_ * H_ * S_ * DH_];  // [B,H,j,DH]   compacted
__device__ __half g_attnh[(size_t)B_ * S_ * D_];     // [B*S, D]
__device__ int    g_kidx[(size_t)B_ * S_];           // compacted key indices
__device__ int    g_kcnt[B_];                        // kept-key counts

// ---------------- asm helpers ------------------------------------------------
__device__ __forceinline__ uint32_t s2u(const void* p) {
    return (uint32_t)__cvta_generic_to_shared(p);
}
__device__ __forceinline__ void cpa16(uint32_t d, const void* s) {
    asm volatile("cp.async.cg.shared.global [%0], [%1], 16;\n" :: "r"(d), "l"(s));
}
__device__ __forceinline__ void cpcommit() {
    asm volatile("cp.async.commit_group;\n");
}
template <int N> __device__ __forceinline__ void cpwait() {
    asm volatile("cp.async.wait_group %0;\n" :: "n"(N));
}
__device__ __forceinline__ void ldm4(unsigned& r0, unsigned& r1, unsigned& r2,
                                     unsigned& r3, uint32_t a) {
    asm volatile("ldmatrix.sync.aligned.m8n8.x4.shared.b16 {%0,%1,%2,%3},[%4];"
                 : "=r"(r0), "=r"(r1), "=r"(r2), "=r"(r3) : "r"(a));
}
__device__ __forceinline__ void ldm4t(unsigned& r0, unsigned& r1, unsigned& r2,
                                      unsigned& r3, uint32_t a) {
    asm volatile("ldmatrix.sync.aligned.m8n8.x4.trans.shared.b16 {%0,%1,%2,%3},[%4];"
                 : "=r"(r0), "=r"(r1), "=r"(r2), "=r"(r3) : "r"(a));
}
__device__ __forceinline__ void mma16(float* c, const unsigned* a, const unsigned* b) {
    asm volatile(
        "mma.sync.aligned.m16n8k16.row.col.f32.f16.f16.f32 "
        "{%0,%1,%2,%3},{%4,%5,%6,%7},{%8,%9},{%0,%1,%2,%3};"
        : "+f"(c[0]), "+f"(c[1]), "+f"(c[2]), "+f"(c[3])
        : "r"(a[0]), "r"(a[1]), "r"(a[2]), "r"(a[3]), "r"(b[0]), "r"(b[1]));
}

// ============================================================================
// Fused prep: X/W conversions (8 float4 per thread; 1540 blocks) + compaction.
// grid: [0,1024) X, [1024,1408) Wqkv, [1408,1536) Wproj, [1536,1540) kidx
// ============================================================================
__global__ void prep_kernel(const float* __restrict__ inp,
                            const float* __restrict__ Wqkv,
                            const float* __restrict__ Wproj,
                            const int* __restrict__ mask)
{
    const int blk = blockIdx.x;
    const int tid = threadIdx.x;

    if (blk < 1024) {                       // X: [S,B,D] fp32 -> [B*S,D] fp16
#pragma unroll
        for (int it = 0; it < 8; ++it) {
            int idx = blk * 2048 + it * 256 + tid;
            int d4 = idx & 255;
            int t  = idx >> 8;
            int b  = t & 3;
            int s  = t >> 2;
            float4 v = *(const float4*)(inp + (((size_t)s * B_ + b) << 10) + d4 * 4);
            __half2* dst = (__half2*)(g_Xh + (((size_t)b * S_ + s) << 10) + d4 * 4);
            dst[0] = __floats2half2_rn(v.x, v.y);
            dst[1] = __floats2half2_rn(v.z, v.w);
        }
    } else if (blk < 1408) {                // Wqkv
#pragma unroll
        for (int it = 0; it < 8; ++it) {
            int idx = (blk - 1024) * 2048 + it * 256 + tid;
            float4 v = *(const float4*)(Wqkv + (size_t)idx * 4);
            __half2* d2 = (__half2*)(g_Wqkvh + (size_t)idx * 4);
            d2[0] = __floats2half2_rn(v.x, v.y);
            d2[1] = __floats2half2_rn(v.z, v.w);
        }
    } else if (blk < 1536) {                // Wproj
#pragma unroll
        for (int it = 0; it < 8; ++it) {
            int idx = (blk - 1408) * 2048 + it * 256 + tid;
            float4 v = *(const float4*)(Wproj + (size_t)idx * 4);
            __half2* d2 = (__half2*)(g_Wprojh + (size_t)idx * 4);
            d2[0] = __floats2half2_rn(v.x, v.y);
            d2[1] = __floats2half2_rn(v.z, v.w);
        }
    } else {                                // key compaction, 1 block / batch
        __shared__ int wsum[8];
        const int b = blk - 1536;
        const int lane = tid & 31, w = tid >> 5;
        const int base = tid * 8;
        int m[8], cnt = 0;
#pragma unroll
        for (int i = 0; i < 8; ++i) {
            m[i] = (mask[(size_t)b * S_ + base + i] == 0);
            cnt += m[i];
        }
        int pre = cnt;
#pragma unroll
        for (int o = 1; o < 32; o <<= 1) {
            int v = __shfl_up_sync(0xffffffffu, pre, o);
            if (lane >= o) pre += v;
        }
        if (lane == 31) wsum[w] = pre;
        __syncthreads();
        if (tid < 8) {
            int v = wsum[tid];
#pragma unroll
            for (int o = 1; o < 8; o <<= 1) {
                int u = __shfl_up_sync(0xffu, v, o);
                if (tid >= o) v += u;
            }
            wsum[tid] = v;
        }
        __syncthreads();
        int excl = pre - cnt + (w > 0 ? wsum[w - 1] : 0);
#pragma unroll
        for (int i = 0; i < 8; ++i)
            if (m[i]) g_kidx[(size_t)b * S_ + excl++] = base + i;
        if (tid == 255) g_kcnt[b] = excl;
    }
}

// ============================================================================
// GEMMs (R13/R11 config: 128 threads, 4 warps 2x2, warp tile 64x64,
// BK=32, 4-stage cp.async, fp32 accumulate, all-fragments-first).
// ============================================================================
constexpr int GSTG = 4;
constexpr int GA_STAGE = 128 * 40;
constexpr size_t GEMM_SMEM_BYTES = (size_t)2 * GSTG * GA_STAGE * 2;   // 80 KB

// QKV GEMM, mask-aware. grid (24, 64). bn<1024: Q mode; else K/V compacted.
__global__ __launch_bounds__(128, 2) void gemm_qkv(const float* __restrict__ bias)
{
    extern __shared__ __half gsm[];
    __half* Asm = gsm;
    __half* Bsm = gsm + GSTG * GA_STAGE;

    const int tid = threadIdx.x, lane = tid & 31, warp = tid >> 5;
    const int lq = lane >> 2, lr = lane & 3;
    const int bn = blockIdx.x * 128;
    const bool QMODE = bn < 1024;
    const int m0w = (warp >> 1) * 64, n0w = (warp & 1) * 64;
    const int crow = tid >> 2, cch = (tid & 3) * 8;

    int bbat = 0, j0 = 0, cnt = 0, bm = 0;
    if (QMODE) {
        bm = blockIdx.y * 128;
    } else {
        bbat = blockIdx.y >> 4;
        j0 = (blockIdx.y & 15) * 128;
        cnt = g_kcnt[bbat];
        if (j0 >= cnt) return;
    }

    const __half* arow[4];
    const __half* wrow[4];
#pragma unroll
    for (int it = 0; it < 4; ++it) {
        int row = crow + it * 32;
        if (QMODE) {
            arow[it] = g_Xh + (size_t)(bm + row) * D_ + cch;
        } else {
            int j = j0 + row;
            int src = (j < cnt) ? g_kidx[(size_t)bbat * S_ + j]
                                : g_kidx[(size_t)bbat * S_];
            arow[it] = g_Xh + ((size_t)bbat * S_ + src) * D_ + cch;
        }
        wrow[it] = g_Wqkvh + (size_t)(bn + row) * D_ + cch;
    }

    float acc[4][8][4];
#pragma unroll
    for (int mt = 0; mt < 4; ++mt)
#pragma unroll
        for (int nt = 0; nt < 8; ++nt)
#pragma unroll
            for (int i = 0; i < 4; ++i) acc[mt][nt][i] = 0.f;

    auto issue = [&](int kt) {
        const int k0 = kt * 32, st = kt & (GSTG - 1);
        __half* Asb = Asm + st * GA_STAGE;
        __half* Bsb = Bsm + st * GA_STAGE;
#pragma unroll
        for (int it = 0; it < 4; ++it) {
            int row = crow + it * 32;
            cpa16(s2u(Asb + row * 40 + cch), arow[it] + k0);
            cpa16(s2u(Bsb + row * 40 + cch), wrow[it] + k0);
        }
    };

    constexpr int NT = D_ / 32;   // 32
    issue(0); cpcommit();
    issue(1); cpcommit();
    issue(2); cpcommit();

#pragma unroll 1
    for (int kt = 0; kt < NT; ++kt) {
        if (kt < NT - 2) cpwait<2>();
        else if (kt == NT - 2) cpwait<1>();
        else cpwait<0>();
        __syncthreads();
        if (kt + 3 < NT) { issue(kt + 3); cpcommit(); }

        const __half* Asb = Asm + (kt & (GSTG - 1)) * GA_STAGE;
        const __half* Bsb = Bsm + (kt & (GSTG - 1)) * GA_STAGE;

        unsigned af[2][4][4], bf[2][8][2];
#pragma unroll
        for (int ks = 0; ks < 2; ++ks) {
            const int acol = ks * 16 + (lane >> 4) * 8;
#pragma unroll
            for (int mt = 0; mt < 4; ++mt) {
                int row = m0w + mt * 16 + (lane & 15);
                ldm4(af[ks][mt][0], af[ks][mt][1], af[ks][mt][2], af[ks][mt][3],
                     s2u(Asb + row * 40 + acol));
            }
#pragma unroll
            for (int ng = 0; ng < 4; ++ng) {
                int row = n0w + ng * 16 + (lane & 7) + ((lane >> 4) << 3);
                int col = ks * 16 + (((lane >> 3) & 1) << 3);
                unsigned r0, r1, r2, r3;
                ldm4(r0, r1, r2, r3, s2u(Bsb + row * 40 + col));
                bf[ks][ng * 2][0] = r0; bf[ks][ng * 2][1] = r1;
                bf[ks][ng * 2 + 1][0] = r2; bf[ks][ng * 2 + 1][1] = r3;
            }
        }
#pragma unroll
        for (int ks = 0; ks < 2; ++ks)
#pragma unroll
            for (int mt = 0; mt < 4; ++mt)
#pragma unroll
                for (int nt = 0; nt < 8; ++nt)
                    mma16(acc[mt][nt], af[ks][mt], bf[ks][nt]);
    }

    // epilogue
#pragma unroll
    for (int mt = 0; mt < 4; ++mt) {
        int rr0 = m0w + mt * 16 + lq;
        int rr1 = rr0 + 8;
#pragma unroll
        for (int nt = 0; nt < 8; ++nt) {
            int c = bn + n0w + nt * 8 + 2 * lr;
            float b0 = bias[c], b1 = bias[c + 1];
            float v00 = acc[mt][nt][0] + b0, v01 = acc[mt][nt][1] + b1;
            float v10 = acc[mt][nt][2] + b0, v11 = acc[mt][nt][3] + b1;
            if (QMODE) {
                int head = c >> 6, dh = c & 63;
                int m0g = bm + rr0, m1g = bm + rr1;
                int b0i = m0g >> 11, s0 = m0g & (S_ - 1);
                int b1i = m1g >> 11, s1 = m1g & (S_ - 1);
                *(__half2*)(g_Qh + (((size_t)b0i * H_ + head) * S_ + s0) * DH_ + dh) =
                    __floats2half2_rn(v00 * SCALE_F, v01 * SCALE_F);
                *(__half2*)(g_Qh + (((size_t)b1i * H_ + head) * S_ + s1) * DH_ + dh) =
                    __floats2half2_rn(v10 * SCALE_F, v11 * SCALE_F);
            } else {
                int n2 = c - 1024;
                int which = n2 >> 10, nn = n2 & (D_ - 1);
                int head = nn >> 6, dh = nn & 63;
                __half* base = (which == 0 ? g_Kh : g_Vh)
                               + ((size_t)bbat * H_ + head) * S_ * DH_ + dh;
                int jr0 = j0 + rr0, jr1 = j0 + rr1;
                if (jr0 < cnt)
                    *(__half2*)(base + (size_t)jr0 * DH_) = __floats2half2_rn(v00, v01);
                if (jr1 < cnt)
                    *(__half2*)(base + (size_t)jr1 * DH_) = __floats2half2_rn(v10, v11);
            }
        }
    }
}

// Projection GEMM: out = g_attnh @ Wproj^T + b
__global__ __launch_bounds__(128, 2) void gemm_proj(
    const float* __restrict__ bias, float* __restrict__ outp)
{
    extern __shared__ __half gsm[];
    __half* Asm = gsm;
    __half* Bsm = gsm + GSTG * GA_STAGE;

    const int tid = threadIdx.x, lane = tid & 31, warp = tid >> 5;
    const int lq = lane >> 2, lr = lane & 3;
    const int bm = blockIdx.y * 128, bn = blockIdx.x * 128;
    const int m0w = (warp >> 1) * 64, n0w = (warp & 1) * 64;
    const int crow = tid >> 2, cch = (tid & 3) * 8;

    float acc[4][8][4];
#pragma unroll
    for (int mt = 0; mt < 4; ++mt)
#pragma unroll
        for (int nt = 0; nt < 8; ++nt)
#pragma unroll
            for (int i = 0; i < 4; ++i) acc[mt][nt][i] = 0.f;

    auto issue = [&](int kt) {
        const int k0 = kt * 32, st = kt & (GSTG - 1);
        __half* Asb = Asm + st * GA_STAGE;
        __half* Bsb = Bsm + st * GA_STAGE;
#pragma unroll
        for (int it = 0; it < 4; ++it) {
            int row = crow + it * 32;
            cpa16(s2u(Asb + row * 40 + cch), g_attnh + (size_t)(bm + row) * D_ + k0 + cch);
            cpa16(s2u(Bsb + row * 40 + cch), g_Wprojh + (size_t)(bn + row) * D_ + k0 + cch);
        }
    };

    constexpr int NT = D_ / 32;
    issue(0); cpcommit();
    issue(1); cpcommit();
    issue(2); cpcommit();

#pragma unroll 1
    for (int kt = 0; kt < NT; ++kt) {
        if (kt < NT - 2) cpwait<2>();
        else if (kt == NT - 2) cpwait<1>();
        else cpwait<0>();
        __syncthreads();
        if (kt + 3 < NT) { issue(kt + 3); cpcommit(); }

        const __half* Asb = Asm + (kt & (GSTG - 1)) * GA_STAGE;
        const __half* Bsb = Bsm + (kt & (GSTG - 1)) * GA_STAGE;

        unsigned af[2][4][4], bf[2][8][2];
#pragma unroll
        for (int ks = 0; ks < 2; ++ks) {
            const int acol = ks * 16 + (lane >> 4) * 8;
#pragma unroll
            for (int mt = 0; mt < 4; ++mt) {
                int row = m0w + mt * 16 + (lane & 15);
                ldm4(af[ks][mt][0], af[ks][mt][1], af[ks][mt][2], af[ks][mt][3],
                     s2u(Asb + row * 40 + acol));
            }
#pragma unroll
            for (int ng = 0; ng < 4; ++ng) {
                int row = n0w + ng * 16 + (lane & 7) + ((lane >> 4) << 3);
                int col = ks * 16 + (((lane >> 3) & 1) << 3);
                unsigned r0, r1, r2, r3;
                ldm4(r0, r1, r2, r3, s2u(Bsb + row * 40 + col));
                bf[ks][ng * 2][0] = r0; bf[ks][ng * 2][1] = r1;
                bf[ks][ng * 2 + 1][0] = r2; bf[ks][ng * 2 + 1][1] = r3;
            }
        }
#pragma unroll
        for (int ks = 0; ks < 2; ++ks)
#pragma unroll
            for (int mt = 0; mt < 4; ++mt)
#pragma unroll
                for (int nt = 0; nt < 8; ++nt)
                    mma16(acc[mt][nt], af[ks][mt], bf[ks][nt]);
    }

#pragma unroll
    for (int mt = 0; mt < 4; ++mt) {
        int r0 = bm + m0w + mt * 16 + lq;
        int r1 = r0 + 8;
        int s0 = r0 & (S_ - 1), bb0 = r0 >> 11;
        int s1 = r1 & (S_ - 1), bb1 = r1 >> 11;
#pragma unroll
        for (int nt = 0; nt < 8; ++nt) {
            int c = bn + n0w + nt * 8 + 2 * lr;
            float b0 = bias[c], b1 = bias[c + 1];
            *(float2*)(outp + ((size_t)s0 * B_ + bb0) * D_ + c) =
                make_float2(acc[mt][nt][0] + b0, acc[mt][nt][1] + b1);
            *(float2*)(outp + ((size_t)s1 * B_ + bb1) * D_ + c) =
                make_float2(acc[mt][nt][2] + b0, acc[mt][nt][3] + b1);
        }
    }
}

// ============================================================================
// Flash attention (R13: 128 q-rows, 8 warps x 16 rows, P in registers,
// 4-stage KV cp.async, uniform one-commit-per-iteration protocol).
// ============================================================================
constexpr int AST = 72;
constexpr int KV_STAGE = 64 * AST;
constexpr int ASTG = 4;
constexpr size_t ATTN_SMEM_BYTES =
    (size_t)(128 * AST + ASTG * 2 * KV_STAGE) * 2;   // 92.2 KB

__global__ __launch_bounds__(256, 2) void attn_h()
{
    extern __shared__ __half smh[];
    __half* Qs = smh;                       // 128 x 72
    __half* Ks = smh + 128 * AST;           // 4 x 64 x 72
    __half* Vs = Ks + ASTG * KV_STAGE;      // 4 x 64 x 72

    const int tid = threadIdx.x, lane = tid & 31, warp = tid >> 5;
    const int lq = lane >> 2, lr = lane & 3;
    const int qt = blockIdx.x, h = blockIdx.y, b = blockIdx.z;
    const int m0 = warp * 16;

    const int cnt = g_kcnt[b];
    const int NTb = (cnt + 63) >> 6 > 0 ? (cnt + 63) >> 6 : 1;

    const __half* Qg = g_Qh + (((size_t)b * H_ + h) * S_ + (size_t)qt * 128) * DH_;
    const __half* Kg = g_Kh + ((size_t)b * H_ + h) * S_ * DH_;
    const __half* Vg = g_Vh + ((size_t)b * H_ + h) * S_ * DH_;

    auto issueKV = [&](int kt) {
        const int st = kt & (ASTG - 1);
#pragma unroll
        for (int it = 0; it < 2; ++it) {
            int c = tid + it * 256;
            int row = c >> 3, ch = (c & 7) * 8;
            size_t g = (size_t)(kt * 64 + row) * DH_ + ch;
            cpa16(s2u(Ks + st * KV_STAGE + row * AST + ch), Kg + g);
            cpa16(s2u(Vs + st * KV_STAGE + row * AST + ch), Vg + g);
        }
    };

#pragma unroll
    for (int it = 0; it < 4; ++it) {
        int c = tid + it * 256;
        int row = c >> 3, ch = (c & 7) * 8;
        cpa16(s2u(Qs + row * AST + ch), Qg + (size_t)row * DH_ + ch);
    }
    issueKV(0); cpcommit();
    issueKV(1); cpcommit();
    issueKV(2); cpcommit();

    float oacc[8][4];
#pragma unroll
    for (int nt = 0; nt < 8; ++nt)
#pragma unroll
        for (int i = 0; i < 4; ++i) oacc[nt][i] = 0.f;
    float l0_ = 0.f, l1_ = 0.f;

#pragma unroll 1
    for (int kt = 0; kt < NTb; ++kt) {
        cpwait<2>();
        __syncthreads();
        if (kt + 3 < NTb) issueKV(kt + 3);
        cpcommit();               // exactly one commit per iteration (may be empty)

        const __half* Kb = Ks + (kt & (ASTG - 1)) * KV_STAGE;
        const __half* Vb = Vs + (kt & (ASTG - 1)) * KV_STAGE;
        const int jbase = kt * 64;

        // ---- S = Q K^T ----
        float sacc[8][4];
#pragma unroll
        for (int nt = 0; nt < 8; ++nt)
#pragma unroll
            for (int i = 0; i < 4; ++i) sacc[nt][i] = 0.f;
#pragma unroll
        for (int ks = 0; ks < 4; ++ks) {
            unsigned qa[4];
            {
                int row = m0 + (lane & 15);
                int col = ks * 16 + (lane >> 4) * 8;
                ldm4(qa[0], qa[1], qa[2], qa[3], s2u(Qs + row * AST + col));
            }
            unsigned bf[8][2];
#pragma unroll
            for (int ng = 0; ng < 4; ++ng) {
                int row = ng * 16 + (lane & 7) + ((lane >> 4) << 3);
                int col = ks * 16 + (((lane >> 3) & 1) << 3);
                unsigned r0, r1, r2, r3;
                ldm4(r0, r1, r2, r3, s2u(Kb + row * AST + col));
                bf[ng * 2][0] = r0; bf[ng * 2][1] = r1;
                bf[ng * 2 + 1][0] = r2; bf[ng * 2 + 1][1] = r3;
            }
#pragma unroll
            for (int nt = 0; nt < 8; ++nt)
                mma16(sacc[nt], qa, bf[nt]);
        }

        // ---- exp -> P fragments in registers ----
        unsigned pp[8][2];
        if (jbase + 64 <= cnt) {
#pragma unroll
            for (int nt = 0; nt < 8; ++nt) {
                float p00 = __expf(sacc[nt][0]);
                float p01 = __expf(sacc[nt][1]);
                float p10 = __expf(sacc[nt][2]);
                float p11 = __expf(sacc[nt][3]);
                l0_ += p00 + p01; l1_ += p10 + p11;
                __half2 h0 = __floats2half2_rn(p00, p01);
                __half2 h1 = __floats2half2_rn(p10, p11);
                pp[nt][0] = *(unsigned*)&h0;
                pp[nt][1] = *(unsigned*)&h1;
            }
        } else {
#pragma unroll
            for (int nt = 0; nt < 8; ++nt) {
                int c = nt * 8 + 2 * lr;
                bool k0v = (jbase + c) < cnt, k1v = (jbase + c + 1) < cnt;
                float p00 = k0v ? __expf(sacc[nt][0]) : 0.f;
                float p01 = k1v ? __expf(sacc[nt][1]) : 0.f;
                float p10 = k0v ? __expf(sacc[nt][2]) : 0.f;
                float p11 = k1v ? __expf(sacc[nt][3]) : 0.f;
                l0_ += p00 + p01; l1_ += p10 + p11;
                __half2 h0 = __floats2half2_rn(p00, p01);
                __half2 h1 = __floats2half2_rn(p10, p11);
                pp[nt][0] = *(unsigned*)&h0;
                pp[nt][1] = *(unsigned*)&h1;
            }
        }

        // ---- O += P V  (P from registers) ----
#pragma unroll
        for (int ks = 0; ks < 4; ++ks) {
            unsigned pa[4] = {pp[2 * ks][0], pp[2 * ks][1],
                              pp[2 * ks + 1][0], pp[2 * ks + 1][1]};
            unsigned bf[8][2];
#pragma unroll
            for (int ng = 0; ng < 4; ++ng) {
                int row = ks * 16 + (lane & 7) + (((lane >> 3) & 1) << 3);
                int col = ng * 16 + (lane >> 4) * 8;
                unsigned r0, r1, r2, r3;
                ldm4t(r0, r1, r2, r3, s2u(Vb + row * AST + col));
                bf[ng * 2][0] = r0; bf[ng * 2][1] = r1;
                bf[ng * 2 + 1][0] = r2; bf[ng * 2 + 1][1] = r3;
            }
#pragma unroll
            for (int nt = 0; nt < 8; ++nt)
                mma16(oacc[nt], pa, bf[nt]);
        }
    }

    // reduce l over the lr quad
    l0_ += __shfl_xor_sync(0xffffffffu, l0_, 1);
    l0_ += __shfl_xor_sync(0xffffffffu, l0_, 2);
    l1_ += __shfl_xor_sync(0xffffffffu, l1_, 1);
    l1_ += __shfl_xor_sync(0xffffffffu, l1_, 2);

    float inv0 = (l0_ > 0.f) ? 1.f / l0_ : 0.f;
    float inv1 = (l1_ > 0.f) ? 1.f / l1_ : 0.f;
    int q0 = qt * 128 + m0 + lq;
    int q1 = q0 + 8;
    __half* O0 = g_attnh + ((size_t)b * S_ + q0) * D_ + h * DH_;
    __half* O1 = g_attnh + ((size_t)b * S_ + q1) * D_ + h * DH_;
#pragma unroll
    for (int nt = 0; nt < 8; ++nt) {
        int c = nt * 8 + 2 * lr;
        *(__half2*)(O0 + c) = __floats2half2_rn(oacc[nt][0] * inv0, oacc[nt][1] * inv0);
        *(__half2*)(O1 + c) = __floats2half2_rn(oacc[nt][2] * inv1, oacc[nt][3] * inv1);
    }
}

// ============================================================================
extern "C" void kernel_launch(void* const* d_in, const int* in_sizes, int n_in,
                              void* d_out, int out_size)
{
    (void)in_sizes; (void)n_in; (void)out_size;
    const float* inp   = (const float*)d_in[0];   // [S,B,D]
    const int*   amask = (const int*)d_in[1];     // [B,S]
    const float* Wqkv  = (const float*)d_in[2];   // [3D,D]
    const float* bqkv  = (const float*)d_in[3];   // [3D]
    const float* Wproj = (const float*)d_in[4];   // [D,D]
    const float* bproj = (const float*)d_in[5];   // [D]
    float* out = (float*)d_out;                   // [S,B,D]

    cudaFuncSetAttribute(gemm_qkv, cudaFuncAttributeMaxDynamicSharedMemorySize,
                         (int)GEMM_SMEM_BYTES);
    cudaFuncSetAttribute(gemm_proj, cudaFuncAttributeMaxDynamicSharedMemorySize,
                         (int)GEMM_SMEM_BYTES);
    cudaFuncSetAttribute(attn_h, cudaFuncAttributeMaxDynamicSharedMemorySize,
                         (int)ATTN_SMEM_BYTES);

    prep_kernel<<<1540, 256>>>(inp, Wqkv, Wproj, amask);
    gemm_qkv<<<dim3(24, 64), 128, GEMM_SMEM_BYTES>>>(bqkv);
    attn_h<<<dim3(S_ / 128, H_, B_), 256, ATTN_SMEM_BYTES>>>();
    gemm_proj<<<dim3(8, 64), 128, GEMM_SMEM_BYTES>>>(bproj, out);
}